// round 15
// baseline (speedup 1.0000x reference)
#include <cuda_runtime.h>
#include <cuda_bf16.h>

#define BB 8
#define T 32768
#define R 64
#define S 128
#define NBLK 24
#define TT 128
#define SB 36               // u32 words per timestep row (32 ch-pairs + 4 pad)
#define HXW (256 * SB)      // words per hx plane (extended window, max width 256)
#define ANW (128 * SB)      // words per a/z plane (width 128)

typedef unsigned int u32;
typedef unsigned short u16;

__device__ __align__(16) float g_h[2][BB * R * T];   // ping-pong fp32 residual stream
__device__ __align__(16) float g_skip[BB * S * T];   // fp32 skip accumulator

// Fragment-ordered bf16 weights (packed pairs), hi + lo split, built by prep_kernel.
#define Q1N 4096
#define Q2N 4096
#define Q3N 6144
__device__ __align__(16) u32 g_q1h[NBLK * Q1N], g_q1l[NBLK * Q1N];
__device__ __align__(16) u32 g_q2h[NBLK * Q2N], g_q2l[NBLK * Q2N];
__device__ __align__(16) u32 g_q3h[NBLK * Q3N], g_q3l[NBLK * Q3N];

__device__ __forceinline__ float fast_tanh(float x) {
    x = fminf(fmaxf(x, -15.f), 15.f);
    float e = __expf(2.f * x);
    return __fdividef(e - 1.f, e + 1.f);
}
__device__ __forceinline__ float fast_sig(float x) {
    return __fdividef(1.f, 1.f + __expf(-x));
}

__device__ __forceinline__ void split2(float v, u16 &h, u16 &lo) {
    __nv_bfloat16 bh = __float2bfloat16_rn(v);
    h = __bfloat16_as_ushort(bh);
    lo = __bfloat16_as_ushort(__float2bfloat16_rn(v - __bfloat162float(bh)));
}

// store fp32 value as bf16 hi/lo into a width-128 packed tensor (plane stride ANW)
__device__ __forceinline__ void store_split(u32* hiBase, int c, int r, float v) {
    u16 h, lo;
    split2(v, h, lo);
    ((u16*)hiBase)[c * (2 * SB) + r] = h;
    ((u16*)(hiBase + ANW))[c * (2 * SB) + r] = lo;
}

#define MMAB(d, a, b0, b1) \
    asm("mma.sync.aligned.m16n8k16.row.col.f32.bf16.bf16.f32 " \
        "{%0,%1,%2,%3}, {%4,%5,%6,%7}, {%8,%9}, {%0,%1,%2,%3};" \
        : "+f"(d[0]), "+f"(d[1]), "+f"(d[2]), "+f"(d[3]) \
        : "r"(a.x), "r"(a.y), "r"(a.z), "r"(a.w), "r"(b0), "r"(b1))

#define MMA3(d, Ah, Al, bh0, bh1, bl0, bl1) do { \
    MMAB(d, Ah, bh0, bh1);                       \
    MMAB(d, Ah, bl0, bl1);                       \
    MMAB(d, Al, bh0, bh1);                       \
} while (0)

__device__ __forceinline__ void fma4(float4 &a, float w, const float4 &v) {
    a.x = fmaf(w, v.x, a.x); a.y = fmaf(w, v.y, a.y);
    a.z = fmaf(w, v.z, a.z); a.w = fmaf(w, v.w, a.w);
}

// ---------------------------------------------------------------------------
// Prep: fragment-ordered bf16 hi/lo weight pairs (once per launch)
// ---------------------------------------------------------------------------
__global__ void prep_kernel(const float* __restrict__ wc, const float* __restrict__ wf,
                            const float* __restrict__ wg, const float* __restrict__ wr,
                            const float* __restrict__ ws) {
    int idx = blockIdx.x * blockDim.x + threadIdx.x;
    const int PER = Q1N + Q2N + Q3N;
    if (idx >= NBLK * PER) return;
    int lyr = idx / PER;
    int e = idx % PER;
    float w0, w1; u32 *dh, *dl;
    if (e < Q1N) {
        int slab = e >> 10, kt = (e >> 7) & 7, lane = (e >> 2) & 31, r = e & 3;
        int row = slab * 16 + (lane >> 2) + 8 * (r & 1);
        int k = kt * 16 + 2 * (lane & 3) + 8 * (r >> 1);
        #define WC(kk) ((kk) < 64 ? wc[(((size_t)lyr * 64 + row) * 64 + (kk)) * 2] \
                                  : wc[(((size_t)lyr * 64 + row) * 64 + (kk) - 64) * 2 + 1])
        w0 = WC(k); w1 = WC(k + 1);
        #undef WC
        dh = g_q1h + (size_t)lyr * Q1N + e;
        dl = g_q1l + (size_t)lyr * Q1N + e;
    } else if (e < Q1N + Q2N) {
        int e2 = e - Q1N;
        int slab = e2 >> 9, kt = (e2 >> 7) & 3, lane = (e2 >> 2) & 31, r = e2 & 3;
        int row = (lane >> 2) + 8 * (r & 1);
        int ch = slab * 8 + (row & 7);
        int k = kt * 16 + 2 * (lane & 3) + 8 * (r >> 1);
        const float* src = (row < 8) ? wf : wg;
        w0 = src[((size_t)lyr * 64 + ch) * 64 + k];
        w1 = src[((size_t)lyr * 64 + ch) * 64 + k + 1];
        dh = g_q2h + (size_t)lyr * Q2N + e2;
        dl = g_q2l + (size_t)lyr * Q2N + e2;
    } else {
        int e3 = e - Q1N - Q2N;
        int slab = e3 >> 9, kt = (e3 >> 7) & 3, lane = (e3 >> 2) & 31, r = e3 & 3;
        int grow = slab * 16 + (lane >> 2) + 8 * (r & 1);
        int k = kt * 16 + 2 * (lane & 3) + 8 * (r >> 1);
        if (grow < 64) {
            w0 = wr[((size_t)lyr * 64 + grow) * 64 + k];
            w1 = wr[((size_t)lyr * 64 + grow) * 64 + k + 1];
        } else {
            w0 = ws[((size_t)lyr * 128 + grow - 64) * 64 + k];
            w1 = ws[((size_t)lyr * 128 + grow - 64) * 64 + k + 1];
        }
        dh = g_q3h + (size_t)lyr * Q3N + e3;
        dl = g_q3l + (size_t)lyr * Q3N + e3;
    }
    u16 h0, l0, h1, l1;
    split2(w0, h0, l0);
    split2(w1, h1, l1);
    *dh = ((u32)h1 << 16) | h0;
    *dl = ((u32)l1 << 16) | l0;
}

// ---------------------------------------------------------------------------
// Kernel 1: input 1x1 conv
// ---------------------------------------------------------------------------
__global__ void input_kernel(const float* __restrict__ x,
                             const float* __restrict__ w_in,
                             const float* __restrict__ b_in) {
    int idx = blockIdx.x * blockDim.x + threadIdx.x;
    int t = idx & (T - 1);
    int r = (idx >> 15) & (R - 1);
    int b = idx >> 21;
    g_h[0][idx] = fmaf(__ldg(&w_in[r]), __ldg(&x[b * T + t]), __ldg(&b_in[r]));
}

// ---------------------------------------------------------------------------
// Kernel 2: fused WaveNet block, bf16 m16n8k16 3-product.
// - Single extended activation window hx[t'] = h(t0-d+t'), width TT+d:
//   hp = hx + 0, hn = hx + d*SB (pointer shift) -> no duplicate load/split.
// - Phase-0 loads coalesced along t (t lane-varying).
// - Phase 3: 6 slabs/warp, jh-split -> B read 2x instead of 4x.
// ---------------------------------------------------------------------------
__global__ void __launch_bounds__(256, 2) block_kernel(
    const float* __restrict__ h_in, float* __restrict__ h_out,
    const uint4* __restrict__ q1h, const uint4* __restrict__ q1l, const float* __restrict__ bc,
    const uint4* __restrict__ q2h, const uint4* __restrict__ q2l, const float* __restrict__ bf,
    const float* __restrict__ bg,
    const uint4* __restrict__ q3h, const uint4* __restrict__ q3l, const float* __restrict__ br,
    const float* __restrict__ bs,
    int d, int first)
{
    extern __shared__ u32 sm32[];
    u32* s_hx = sm32;               // extended h window: hi; lo at +HXW (dead after P1)
    u32* s_a  = sm32;               // 'a' tensor (reuses hx): hi; lo at +ANW
    u32* s_z  = sm32 + 2 * HXW;     // z: hi; lo at +ANW

    const int b = blockIdx.y, t0 = blockIdx.x * TT;
    const int tid = threadIdx.x, wp = tid >> 5, l = tid & 31;
    const int lk = l & 3, ln = l >> 2;
    const float* hbase = h_in + (size_t)b * R * T;

    // ---- Phase 0: load h window [t0-d, t0+TT), split, coalesced along t ----
    {
        const int W = TT + d;
        for (int idx = tid; idx < 32 * 256; idx += 256) {
            int t = idx & 255, rp = idx >> 8;
            if (t < W) {
                int ts = t0 - d + t;
                float a0 = 0.f, a1 = 0.f;
                if (ts >= 0) {
                    a0 = hbase[(size_t)(2 * rp) * T + ts];
                    a1 = hbase[(size_t)(2 * rp + 1) * T + ts];
                }
                u16 h0, l0, h1, l1;
                split2(a0, h0, l0);
                split2(a1, h1, l1);
                s_hx[t * SB + rp] = ((u32)h1 << 16) | h0;
                s_hx[t * SB + rp + HXW] = ((u32)l1 << 16) | l0;
            }
        }
    }
    __syncthreads();

    // ---- Phase 1: z = Wc x [hp; hn]  (2 slabs x 32 cols per warp) ----
    {
        const int mg = wp >> 2, cg = wp & 3;
        const int cb = cg * 32;
        const int s0 = 2 * mg, s1 = s0 + 1;
        float acc0[4][4], acc1[4][4];
        #pragma unroll
        for (int j = 0; j < 4; j++) {
            acc0[j][0] = acc0[j][1] = acc0[j][2] = acc0[j][3] = 0.f;
            acc1[j][0] = acc1[j][1] = acc1[j][2] = acc1[j][3] = 0.f;
        }
        #pragma unroll 2
        for (int kt = 0; kt < 8; kt++) {
            uint4 Ah0 = __ldg(&q1h[(s0 * 8 + kt) * 32 + l]);
            uint4 Al0 = __ldg(&q1l[(s0 * 8 + kt) * 32 + l]);
            uint4 Ah1 = __ldg(&q1h[(s1 * 8 + kt) * 32 + l]);
            uint4 Al1 = __ldg(&q1l[(s1 * 8 + kt) * 32 + l]);
            // kt<4: prev tap reads hx (=h shifted by d); kt>=4: current tap at +d cols
            const u32* bh = s_hx + (kt & 3) * 8 + lk
                          + (cb + ln + ((kt < 4) ? 0 : d)) * SB;
            #pragma unroll
            for (int j = 0; j < 4; j++) {
                u32 bh0 = bh[j * 8 * SB], bh1 = bh[j * 8 * SB + 4];
                u32 bl0 = bh[j * 8 * SB + HXW], bl1 = bh[j * 8 * SB + HXW + 4];
                MMA3(acc0[j], Ah0, Al0, bh0, bh1, bl0, bl1);
                MMA3(acc1[j], Ah1, Al1, bh0, bh1, bl0, bl1);
            }
        }
        #pragma unroll
        for (int si = 0; si < 2; si++) {
            float (*ac)[4] = si ? acc1 : acc0;
            int r0 = (2 * mg + si) * 16 + ln;
            float bv0 = __ldg(bc + r0), bv1 = __ldg(bc + r0 + 8);
            #pragma unroll
            for (int j = 0; j < 4; j++) {
                int c0 = cb + j * 8 + 2 * lk;
                store_split(s_z, c0,     r0,     ac[j][0] + bv0);
                store_split(s_z, c0 + 1, r0,     ac[j][1] + bv0);
                store_split(s_z, c0,     r0 + 8, ac[j][2] + bv1);
                store_split(s_z, c0 + 1, r0 + 8, ac[j][3] + bv1);
            }
        }
    }
    __syncthreads();   // hx dead from here; s_a region writable

    // ---- Phase 2: a = tanh(Wf z + bf) * sigmoid(Wg z + bg)  (4 slabs x 32 cols) ----
    {
        const int mg = wp >> 2, cg = wp & 3;
        const int cb = cg * 32;
        float acc[4][4][4];
        #pragma unroll
        for (int si = 0; si < 4; si++)
            #pragma unroll
            for (int j = 0; j < 4; j++)
                acc[si][j][0] = acc[si][j][1] = acc[si][j][2] = acc[si][j][3] = 0.f;
        #pragma unroll
        for (int kt = 0; kt < 4; kt++) {
            uint4 Ah[4], Al[4];
            #pragma unroll
            for (int si = 0; si < 4; si++) {
                int slab = 4 * mg + si;
                Ah[si] = __ldg(&q2h[(slab * 4 + kt) * 32 + l]);
                Al[si] = __ldg(&q2l[(slab * 4 + kt) * 32 + l]);
            }
            const u32* bh = s_z + kt * 8 + lk + (cb + ln) * SB;
            #pragma unroll
            for (int j = 0; j < 4; j++) {
                u32 bh0 = bh[j * 8 * SB], bh1 = bh[j * 8 * SB + 4];
                u32 bl0 = bh[j * 8 * SB + ANW], bl1 = bh[j * 8 * SB + ANW + 4];
                #pragma unroll
                for (int si = 0; si < 4; si++)
                    MMA3(acc[si][j], Ah[si], Al[si], bh0, bh1, bl0, bl1);
            }
        }
        #pragma unroll
        for (int si = 0; si < 4; si++) {
            int slab = 4 * mg + si;
            int ch = slab * 8 + ln;
            float bfv = __ldg(bf + ch), bgv = __ldg(bg + ch);
            #pragma unroll
            for (int j = 0; j < 4; j++) {
                int c0 = cb + j * 8 + 2 * lk;
                float a0 = fast_tanh(acc[si][j][0] + bfv) * fast_sig(acc[si][j][2] + bgv);
                float a1 = fast_tanh(acc[si][j][1] + bfv) * fast_sig(acc[si][j][3] + bgv);
                store_split(s_a, c0,     ch, a0);
                store_split(s_a, c0 + 1, ch, a1);
            }
        }
    }
    __syncthreads();

    // ---- Phase 3: res (slabs 0-3) + skip (slabs 4-11); 6 slabs/warp, jh-split ----
    {
        float* hdst = h_out + (size_t)b * R * T + t0;
        const float* hsrc = h_in + (size_t)b * R * T + t0;
        float* skp = g_skip + (size_t)b * S * T + t0;
        const int mg = wp >> 2, cg = wp & 3;
        const int cb = cg * 32;
        #pragma unroll
        for (int jh = 0; jh < 2; jh++) {
            float acc[6][2][4];
            #pragma unroll
            for (int si = 0; si < 6; si++)
                #pragma unroll
                for (int jj = 0; jj < 2; jj++)
                    acc[si][jj][0] = acc[si][jj][1] = acc[si][jj][2] = acc[si][jj][3] = 0.f;
            #pragma unroll
            for (int kt = 0; kt < 4; kt++) {
                uint4 Ah[6], Al[6];
                #pragma unroll
                for (int si = 0; si < 6; si++) {
                    int slab = 6 * mg + si;
                    Ah[si] = __ldg(&q3h[(slab * 4 + kt) * 32 + l]);
                    Al[si] = __ldg(&q3l[(slab * 4 + kt) * 32 + l]);
                }
                const u32* bh = s_a + kt * 8 + lk + (cb + ln) * SB;
                #pragma unroll
                for (int jj = 0; jj < 2; jj++) {
                    int j = jh * 2 + jj;
                    u32 bh0 = bh[j * 8 * SB], bh1 = bh[j * 8 * SB + 4];
                    u32 bl0 = bh[j * 8 * SB + ANW], bl1 = bh[j * 8 * SB + ANW + 4];
                    #pragma unroll
                    for (int si = 0; si < 6; si++)
                        MMA3(acc[si][jj], Ah[si], Al[si], bh0, bh1, bl0, bl1);
                }
            }
            #pragma unroll
            for (int si = 0; si < 6; si++) {
                int slab = 6 * mg + si;
                int r0 = slab * 16 + ln;
                if (r0 < 64) {
                    float br0 = __ldg(br + r0), br1 = __ldg(br + r0 + 8);
                    #pragma unroll
                    for (int jj = 0; jj < 2; jj++) {
                        int c0 = cb + (jh * 2 + jj) * 8 + 2 * lk;
                        float2 h0 = *(const float2*)(hsrc + (size_t)r0 * T + c0);
                        float2 h1 = *(const float2*)(hsrc + (size_t)(r0 + 8) * T + c0);
                        float2 v0 = { acc[si][jj][0] + br0 + h0.x, acc[si][jj][1] + br0 + h0.y };
                        float2 v1 = { acc[si][jj][2] + br1 + h1.x, acc[si][jj][3] + br1 + h1.y };
                        *(float2*)(hdst + (size_t)r0 * T + c0) = v0;
                        *(float2*)(hdst + (size_t)(r0 + 8) * T + c0) = v1;
                    }
                } else {
                    int sk0 = r0 - 64;
                    float bs0 = __ldg(bs + sk0), bs1 = __ldg(bs + sk0 + 8);
                    #pragma unroll
                    for (int jj = 0; jj < 2; jj++) {
                        int c0 = cb + (jh * 2 + jj) * 8 + 2 * lk;
                        float2* g0 = (float2*)(skp + (size_t)sk0 * T + c0);
                        float2* g1 = (float2*)(skp + (size_t)(sk0 + 8) * T + c0);
                        float2 v0 = { acc[si][jj][0] + bs0, acc[si][jj][1] + bs0 };
                        float2 v1 = { acc[si][jj][2] + bs1, acc[si][jj][3] + bs1 };
                        if (!first) {
                            float2 o0 = *g0, o1 = *g1;
                            v0.x += o0.x; v0.y += o0.y; v1.x += o1.x; v1.y += o1.y;
                        }
                        *g0 = v0; *g1 = v1;
                    }
                }
            }
        }
    }
}

// ---------------------------------------------------------------------------
// Kernel 3: head (fp32)
// ---------------------------------------------------------------------------
__global__ void __launch_bounds__(256) head_kernel(
    const float* __restrict__ w1, const float* __restrict__ b1,
    const float* __restrict__ w2, const float* __restrict__ b2,
    float* __restrict__ out)
{
    extern __shared__ float smem[];
    float* sk   = smem;
    float* part = smem + S * TT;

    const int b = blockIdx.y, t0 = blockIdx.x * TT;
    const int tid = threadIdx.x, wp = tid >> 5, l = tid & 31;
    const float* skg = g_skip + (size_t)b * S * T + t0;

    for (int f = tid; f < S * TT / 4; f += 256) {
        int row = f >> 5, col = f & 31;
        float4 v = ((const float4*)(skg + (size_t)row * T))[col];
        v.x = fmaxf(v.x, 0.f); v.y = fmaxf(v.y, 0.f);
        v.z = fmaxf(v.z, 0.f); v.w = fmaxf(v.w, 0.f);
        ((float4*)sk)[f] = v;
    }
    __syncthreads();

    const float4* sk4 = (const float4*)sk;
    float4 po = {0.f, 0.f, 0.f, 0.f};
    for (int s2 = wp * 16; s2 < wp * 16 + 16; s2++) {
        float4 u = {0.f, 0.f, 0.f, 0.f};
        const float* wrow = w1 + (s2 << 7);
        #pragma unroll 8
        for (int s1 = 0; s1 < S; s1++)
            fma4(u, __ldg(wrow + s1), sk4[(s1 << 5) + l]);
        float bb = __ldg(b1 + s2);
        u.x = fmaxf(u.x + bb, 0.f); u.y = fmaxf(u.y + bb, 0.f);
        u.z = fmaxf(u.z + bb, 0.f); u.w = fmaxf(u.w + bb, 0.f);
        fma4(po, __ldg(w2 + s2), u);
    }
    ((float4*)(part + wp * TT))[l] = po;
    __syncthreads();

    if (tid < TT) {
        float acc = __ldg(b2);
        #pragma unroll
        for (int ww = 0; ww < 8; ww++) acc += part[ww * TT + tid];
        out[(size_t)b * T + t0 + tid] = acc;
    }
}

// ---------------------------------------------------------------------------
extern "C" void kernel_launch(void* const* d_in, const int* in_sizes, int n_in,
                              void* d_out, int out_size) {
    const float* x        = (const float*)d_in[0];
    const float* w_in     = (const float*)d_in[1];
    const float* b_in     = (const float*)d_in[2];
    const float* w_causal = (const float*)d_in[3];
    const float* b_causal = (const float*)d_in[4];
    const float* w_filter = (const float*)d_in[5];
    const float* b_filter = (const float*)d_in[6];
    const float* w_gate   = (const float*)d_in[7];
    const float* b_gate   = (const float*)d_in[8];
    const float* w_res    = (const float*)d_in[9];
    const float* b_res    = (const float*)d_in[10];
    const float* w_skip   = (const float*)d_in[11];
    const float* b_skip   = (const float*)d_in[12];
    const float* w_out1   = (const float*)d_in[13];
    const float* b_out1   = (const float*)d_in[14];
    const float* w_out2   = (const float*)d_in[15];
    const float* b_out2   = (const float*)d_in[16];
    float* out = (float*)d_out;

    const int blk_smem  = (2 * HXW + 2 * ANW) * 4;   // 110,592 B -> 2 CTAs/SM
    const int head_smem = (S * TT + 8 * TT) * 4;     // 68 KB
    cudaFuncSetAttribute(block_kernel, cudaFuncAttributeMaxDynamicSharedMemorySize, blk_smem);
    cudaFuncSetAttribute(head_kernel,  cudaFuncAttributeMaxDynamicSharedMemorySize, head_smem);

    float* hbuf0;
    u32 *q1h, *q1l, *q2h, *q2l, *q3h, *q3l;
    cudaGetSymbolAddress((void**)&hbuf0, g_h);
    cudaGetSymbolAddress((void**)&q1h, g_q1h);
    cudaGetSymbolAddress((void**)&q1l, g_q1l);
    cudaGetSymbolAddress((void**)&q2h, g_q2h);
    cudaGetSymbolAddress((void**)&q2l, g_q2l);
    cudaGetSymbolAddress((void**)&q3h, g_q3h);
    cudaGetSymbolAddress((void**)&q3l, g_q3l);
    float* hbuf[2] = { hbuf0, hbuf0 + (size_t)BB * R * T };

    const int pre_total = NBLK * (Q1N + Q2N + Q3N);
    prep_kernel<<<(pre_total + 255) / 256, 256>>>(w_causal, w_filter, w_gate, w_res, w_skip);

    input_kernel<<<BB * R * T / 256, 256>>>(x, w_in, b_in);

    dim3 grid(T / TT, BB);
    for (int i = 0; i < NBLK; i++) {
        int d = 1 << (i & 7);
        block_kernel<<<grid, 256, blk_smem>>>(
            hbuf[i & 1], hbuf[(i + 1) & 1],
            (const uint4*)(q1h + (size_t)i * Q1N), (const uint4*)(q1l + (size_t)i * Q1N),
            b_causal + (size_t)i * R,
            (const uint4*)(q2h + (size_t)i * Q2N), (const uint4*)(q2l + (size_t)i * Q2N),
            b_filter + (size_t)i * R, b_gate + (size_t)i * R,
            (const uint4*)(q3h + (size_t)i * Q3N), (const uint4*)(q3l + (size_t)i * Q3N),
            b_res + (size_t)i * R, b_skip + (size_t)i * S,
            d, i == 0 ? 1 : 0);
    }

    head_kernel<<<grid, 256, head_smem>>>(w_out1, b_out1, w_out2, b_out2, out);
}

// round 16
// speedup vs baseline: 1.3198x; 1.3198x over previous
#include <cuda_runtime.h>
#include <cuda_bf16.h>

#define BB 8
#define T 32768
#define R 64
#define S 128
#define NBLK 24
#define TT 128
#define SB 36              // u32 words per timestep row (32 ch-pairs + 4 pad)
#define TNW (128 * SB)     // words per tensor plane (hi or lo) = 4608

typedef unsigned int u32;
typedef unsigned short u16;

__device__ __align__(16) float g_h[2][BB * R * T];   // ping-pong fp32 residual stream
__device__ __align__(16) float g_skip[BB * S * T];   // fp32 skip accumulator

// Fragment-ordered bf16 weights (packed pairs), hi + lo split, built by prep_kernel.
#define Q1N 4096
#define Q2N 4096
#define Q3N 6144
__device__ __align__(16) u32 g_q1h[NBLK * Q1N], g_q1l[NBLK * Q1N];
__device__ __align__(16) u32 g_q2h[NBLK * Q2N], g_q2l[NBLK * Q2N];
__device__ __align__(16) u32 g_q3h[NBLK * Q3N], g_q3l[NBLK * Q3N];

// MUFU-based gated activation (error ~1e-6, negligible vs bf16-split 2^-18 scheme)
__device__ __forceinline__ float fast_tanh(float x) {
    x = fminf(fmaxf(x, -15.f), 15.f);
    float e = __expf(2.f * x);
    return __fdividef(e - 1.f, e + 1.f);
}
__device__ __forceinline__ float fast_sig(float x) {
    return __fdividef(1.f, 1.f + __expf(-x));
}

__device__ __forceinline__ void split2(float v, u16 &h, u16 &lo) {
    __nv_bfloat16 bh = __float2bfloat16_rn(v);
    h = __bfloat16_as_ushort(bh);
    lo = __bfloat16_as_ushort(__float2bfloat16_rn(v - __bfloat162float(bh)));
}

// store fp32 value as bf16 hi/lo into packed-u16 tensor planes at (channel r, time c)
__device__ __forceinline__ void store_split(u32* hiBase, int c, int r, float v) {
    u16 h, lo;
    split2(v, h, lo);
    ((u16*)hiBase)[c * (2 * SB) + r] = h;
    ((u16*)(hiBase + TNW))[c * (2 * SB) + r] = lo;
}

#define MMAB(d, a, b0, b1) \
    asm("mma.sync.aligned.m16n8k16.row.col.f32.bf16.bf16.f32 " \
        "{%0,%1,%2,%3}, {%4,%5,%6,%7}, {%8,%9}, {%0,%1,%2,%3};" \
        : "+f"(d[0]), "+f"(d[1]), "+f"(d[2]), "+f"(d[3]) \
        : "r"(a.x), "r"(a.y), "r"(a.z), "r"(a.w), "r"(b0), "r"(b1))

// 3-product bf16 scheme: Ah*Bh + Ah*Bl + Al*Bh
#define MMA3(d, Ah, Al, bh0, bh1, bl0, bl1) do { \
    MMAB(d, Ah, bh0, bh1);                       \
    MMAB(d, Ah, bl0, bl1);                       \
    MMAB(d, Al, bh0, bh1);                       \
} while (0)

__device__ __forceinline__ void fma4(float4 &a, float w, const float4 &v) {
    a.x = fmaf(w, v.x, a.x); a.y = fmaf(w, v.y, a.y);
    a.z = fmaf(w, v.z, a.z); a.w = fmaf(w, v.w, a.w);
}

// ---------------------------------------------------------------------------
// Prep: fragment-ordered bf16 hi/lo weight pairs (once per launch)
// ---------------------------------------------------------------------------
__global__ void prep_kernel(const float* __restrict__ wc, const float* __restrict__ wf,
                            const float* __restrict__ wg, const float* __restrict__ wr,
                            const float* __restrict__ ws) {
    int idx = blockIdx.x * blockDim.x + threadIdx.x;
    const int PER = Q1N + Q2N + Q3N;
    if (idx >= NBLK * PER) return;
    int lyr = idx / PER;
    int e = idx % PER;
    float w0, w1; u32 *dh, *dl;
    if (e < Q1N) {
        int slab = e >> 10, kt = (e >> 7) & 7, lane = (e >> 2) & 31, r = e & 3;
        int row = slab * 16 + (lane >> 2) + 8 * (r & 1);
        int k = kt * 16 + 2 * (lane & 3) + 8 * (r >> 1);
        #define WC(kk) ((kk) < 64 ? wc[(((size_t)lyr * 64 + row) * 64 + (kk)) * 2] \
                                  : wc[(((size_t)lyr * 64 + row) * 64 + (kk) - 64) * 2 + 1])
        w0 = WC(k); w1 = WC(k + 1);
        #undef WC
        dh = g_q1h + (size_t)lyr * Q1N + e;
        dl = g_q1l + (size_t)lyr * Q1N + e;
    } else if (e < Q1N + Q2N) {
        int e2 = e - Q1N;
        int slab = e2 >> 9, kt = (e2 >> 7) & 3, lane = (e2 >> 2) & 31, r = e2 & 3;
        int row = (lane >> 2) + 8 * (r & 1);           // 0..15 within tile
        int ch = slab * 8 + (row & 7);
        int k = kt * 16 + 2 * (lane & 3) + 8 * (r >> 1);
        const float* src = (row < 8) ? wf : wg;
        w0 = src[((size_t)lyr * 64 + ch) * 64 + k];
        w1 = src[((size_t)lyr * 64 + ch) * 64 + k + 1];
        dh = g_q2h + (size_t)lyr * Q2N + e2;
        dl = g_q2l + (size_t)lyr * Q2N + e2;
    } else {
        int e3 = e - Q1N - Q2N;
        int slab = e3 >> 9, kt = (e3 >> 7) & 3, lane = (e3 >> 2) & 31, r = e3 & 3;
        int grow = slab * 16 + (lane >> 2) + 8 * (r & 1);  // 0..191
        int k = kt * 16 + 2 * (lane & 3) + 8 * (r >> 1);
        if (grow < 64) {
            w0 = wr[((size_t)lyr * 64 + grow) * 64 + k];
            w1 = wr[((size_t)lyr * 64 + grow) * 64 + k + 1];
        } else {
            w0 = ws[((size_t)lyr * 128 + grow - 64) * 64 + k];
            w1 = ws[((size_t)lyr * 128 + grow - 64) * 64 + k + 1];
        }
        dh = g_q3h + (size_t)lyr * Q3N + e3;
        dl = g_q3l + (size_t)lyr * Q3N + e3;
    }
    u16 h0, l0, h1, l1;
    split2(w0, h0, l0);
    split2(w1, h1, l1);
    *dh = ((u32)h1 << 16) | h0;
    *dl = ((u32)l1 << 16) | l0;
}

// ---------------------------------------------------------------------------
// Kernel 1: input 1x1 conv
// ---------------------------------------------------------------------------
__global__ void input_kernel(const float* __restrict__ x,
                             const float* __restrict__ w_in,
                             const float* __restrict__ b_in) {
    int idx = blockIdx.x * blockDim.x + threadIdx.x;
    int t = idx & (T - 1);
    int r = (idx >> 15) & (R - 1);
    int b = idx >> 21;
    g_h[0][idx] = fmaf(__ldg(&w_in[r]), __ldg(&x[b * T + t]), __ldg(&b_in[r]));
}

// ---------------------------------------------------------------------------
// Kernel 2: fused WaveNet block, bf16 m16n8k16 3-product, plane layout.
// R13 tiling (P1: 2 slabs x 32 cols; P2: 4 slabs x 32; P3: 3 slabs x 32 x2).
// Interior P2 barrier removed: P2 MMAs read only s_z, P2 epilogue writes only
// s_hp('a'), last read in P1 behind the post-P1 barrier -> epilogue overlaps
// other warps' MMA tail.
// ---------------------------------------------------------------------------
__global__ void __launch_bounds__(256, 2) block_kernel(
    const float* __restrict__ h_in, float* __restrict__ h_out,
    const uint4* __restrict__ q1h, const uint4* __restrict__ q1l, const float* __restrict__ bc,
    const uint4* __restrict__ q2h, const uint4* __restrict__ q2l, const float* __restrict__ bf,
    const float* __restrict__ bg,
    const uint4* __restrict__ q3h, const uint4* __restrict__ q3l, const float* __restrict__ br,
    const float* __restrict__ bs,
    int d, int first)
{
    extern __shared__ u32 sm32[];
    u32* s_hp = sm32;               // h(t-d) hi; lo at +TNW   (reused as 'a' later)
    u32* s_hn = sm32 + 2 * TNW;     // h(t)   hi; lo at +TNW
    u32* s_z  = sm32 + 4 * TNW;     // z      hi; lo at +TNW

    const int b = blockIdx.y, t0 = blockIdx.x * TT;
    const int tid = threadIdx.x, wp = tid >> 5, l = tid & 31;
    const int lk = l & 3, ln = l >> 2;
    const float* hbase = h_in + (size_t)b * R * T;

    // ---- Phase 0: load fp32 h, bf16-split into packed smem planes ----
    for (int idx = tid; idx < 1024; idx += 256) {
        int rp = idx & 31, c4 = idx >> 5;   // ch-pair, float4 col
        float4 v0 = ((const float4*)(hbase + (size_t)(2 * rp) * T + t0))[c4];
        float4 v1 = ((const float4*)(hbase + (size_t)(2 * rp + 1) * T + t0))[c4];
        const float* e0 = (const float*)&v0;
        const float* e1 = (const float*)&v1;
        #pragma unroll
        for (int i = 0; i < 4; i++) {
            u16 h0, l0, h1, l1;
            split2(e0[i], h0, l0);
            split2(e1[i], h1, l1);
            s_hn[(c4 * 4 + i) * SB + rp] = ((u32)h1 << 16) | h0;
            s_hn[(c4 * 4 + i) * SB + rp + TNW] = ((u32)l1 << 16) | l0;
        }
    }
    if ((d & 3) == 0) {
        const int dq = d >> 2;
        for (int idx = tid; idx < 1024; idx += 256) {
            int rp = idx & 31, c4 = idx >> 5;
            int tq = (t0 >> 2) + c4 - dq;
            float4 v0, v1;
            if (tq >= 0) {
                v0 = ((const float4*)(hbase + (size_t)(2 * rp) * T))[tq];
                v1 = ((const float4*)(hbase + (size_t)(2 * rp + 1) * T))[tq];
            } else {
                v0 = make_float4(0.f, 0.f, 0.f, 0.f);
                v1 = v0;
            }
            const float* e0 = (const float*)&v0;
            const float* e1 = (const float*)&v1;
            #pragma unroll
            for (int i = 0; i < 4; i++) {
                u16 h0, l0, h1, l1;
                split2(e0[i], h0, l0);
                split2(e1[i], h1, l1);
                s_hp[(c4 * 4 + i) * SB + rp] = ((u32)h1 << 16) | h0;
                s_hp[(c4 * 4 + i) * SB + rp + TNW] = ((u32)l1 << 16) | l0;
            }
        }
    } else {
        for (int idx = tid; idx < 4096; idx += 256) {
            int rp = idx & 31, t = idx >> 5;
            int ts = t0 + t - d;
            float a0 = 0.f, a1 = 0.f;
            if (ts >= 0) {
                a0 = hbase[(size_t)(2 * rp) * T + ts];
                a1 = hbase[(size_t)(2 * rp + 1) * T + ts];
            }
            u16 h0, l0, h1, l1;
            split2(a0, h0, l0);
            split2(a1, h1, l1);
            s_hp[t * SB + rp] = ((u32)h1 << 16) | h0;
            s_hp[t * SB + rp + TNW] = ((u32)l1 << 16) | l0;
        }
    }
    __syncthreads();

    // ---- Phase 1: z = Wc x [hp; hn]  (2 slabs x 32 cols per warp) ----
    {
        const int mg = wp >> 2, cg = wp & 3;
        const int cb = cg * 32;
        const int s0 = 2 * mg, s1 = s0 + 1;
        float acc0[4][4], acc1[4][4];
        #pragma unroll
        for (int j = 0; j < 4; j++) {
            acc0[j][0] = acc0[j][1] = acc0[j][2] = acc0[j][3] = 0.f;
            acc1[j][0] = acc1[j][1] = acc1[j][2] = acc1[j][3] = 0.f;
        }
        #pragma unroll 2
        for (int kt = 0; kt < 8; kt++) {
            uint4 Ah0 = __ldg(&q1h[(s0 * 8 + kt) * 32 + l]);
            uint4 Al0 = __ldg(&q1l[(s0 * 8 + kt) * 32 + l]);
            uint4 Ah1 = __ldg(&q1h[(s1 * 8 + kt) * 32 + l]);
            uint4 Al1 = __ldg(&q1l[(s1 * 8 + kt) * 32 + l]);
            const u32* bh = ((kt < 4) ? s_hp : s_hn) + (kt & 3) * 8 + lk + (cb + ln) * SB;
            #pragma unroll
            for (int j = 0; j < 4; j++) {
                u32 bh0 = bh[j * 8 * SB], bh1 = bh[j * 8 * SB + 4];
                u32 bl0 = bh[j * 8 * SB + TNW], bl1 = bh[j * 8 * SB + TNW + 4];
                MMA3(acc0[j], Ah0, Al0, bh0, bh1, bl0, bl1);
                MMA3(acc1[j], Ah1, Al1, bh0, bh1, bl0, bl1);
            }
        }
        #pragma unroll
        for (int si = 0; si < 2; si++) {
            float (*ac)[4] = si ? acc1 : acc0;
            int r0 = (2 * mg + si) * 16 + ln;
            float bv0 = __ldg(bc + r0), bv1 = __ldg(bc + r0 + 8);
            #pragma unroll
            for (int j = 0; j < 4; j++) {
                int c0 = cb + j * 8 + 2 * lk;
                store_split(s_z, c0,     r0,     ac[j][0] + bv0);
                store_split(s_z, c0 + 1, r0,     ac[j][1] + bv0);
                store_split(s_z, c0,     r0 + 8, ac[j][2] + bv1);
                store_split(s_z, c0 + 1, r0 + 8, ac[j][3] + bv1);
            }
        }
    }
    __syncthreads();

    // ---- Phase 2: a = tanh(Wf z + bf) * sigmoid(Wg z + bg)  (4 slabs x 32 cols) ----
    // No interior barrier: MMAs read s_z only; epilogue writes s_hp only.
    {
        const int mg = wp >> 2, cg = wp & 3;
        const int cb = cg * 32;
        float acc[4][4][4];
        #pragma unroll
        for (int si = 0; si < 4; si++)
            #pragma unroll
            for (int j = 0; j < 4; j++)
                acc[si][j][0] = acc[si][j][1] = acc[si][j][2] = acc[si][j][3] = 0.f;
        #pragma unroll
        for (int kt = 0; kt < 4; kt++) {
            uint4 Ah[4], Al[4];
            #pragma unroll
            for (int si = 0; si < 4; si++) {
                int slab = 4 * mg + si;
                Ah[si] = __ldg(&q2h[(slab * 4 + kt) * 32 + l]);
                Al[si] = __ldg(&q2l[(slab * 4 + kt) * 32 + l]);
            }
            const u32* bh = s_z + kt * 8 + lk + (cb + ln) * SB;
            #pragma unroll
            for (int j = 0; j < 4; j++) {
                u32 bh0 = bh[j * 8 * SB], bh1 = bh[j * 8 * SB + 4];
                u32 bl0 = bh[j * 8 * SB + TNW], bl1 = bh[j * 8 * SB + TNW + 4];
                #pragma unroll
                for (int si = 0; si < 4; si++)
                    MMA3(acc[si][j], Ah[si], Al[si], bh0, bh1, bl0, bl1);
            }
        }
        #pragma unroll
        for (int si = 0; si < 4; si++) {
            int slab = 4 * mg + si;
            int ch = slab * 8 + ln;
            float bfv = __ldg(bf + ch), bgv = __ldg(bg + ch);
            #pragma unroll
            for (int j = 0; j < 4; j++) {
                int c0 = cb + j * 8 + 2 * lk;
                float a0 = fast_tanh(acc[si][j][0] + bfv) * fast_sig(acc[si][j][2] + bgv);
                float a1 = fast_tanh(acc[si][j][1] + bfv) * fast_sig(acc[si][j][3] + bgv);
                store_split(s_hp, c0,     ch, a0);   // a overwrites hp
                store_split(s_hp, c0 + 1, ch, a1);
            }
        }
    }
    __syncthreads();

    // ---- Phase 3: res (slabs 0-3) + skip (slabs 4-11)  (3 slabs x 32 cols, x2) ----
    {
        float* hdst = h_out + (size_t)b * R * T + t0;
        const float* hsrc = h_in + (size_t)b * R * T + t0;
        float* skp = g_skip + (size_t)b * S * T + t0;
        #pragma unroll
        for (int ui = 0; ui < 2; ui++) {
            int u = wp + ui * 8;          // 0..15
            int mg = u >> 2, cg = u & 3;
            int cb = cg * 32;
            float acc[3][4][4];
            #pragma unroll
            for (int si = 0; si < 3; si++)
                #pragma unroll
                for (int j = 0; j < 4; j++)
                    acc[si][j][0] = acc[si][j][1] = acc[si][j][2] = acc[si][j][3] = 0.f;
            #pragma unroll
            for (int kt = 0; kt < 4; kt++) {
                uint4 Ah[3], Al[3];
                #pragma unroll
                for (int si = 0; si < 3; si++) {
                    int slab = 3 * mg + si;
                    Ah[si] = __ldg(&q3h[(slab * 4 + kt) * 32 + l]);
                    Al[si] = __ldg(&q3l[(slab * 4 + kt) * 32 + l]);
                }
                const u32* bh = s_hp + kt * 8 + lk + (cb + ln) * SB;
                #pragma unroll
                for (int j = 0; j < 4; j++) {
                    u32 bh0 = bh[j * 8 * SB], bh1 = bh[j * 8 * SB + 4];
                    u32 bl0 = bh[j * 8 * SB + TNW], bl1 = bh[j * 8 * SB + TNW + 4];
                    #pragma unroll
                    for (int si = 0; si < 3; si++)
                        MMA3(acc[si][j], Ah[si], Al[si], bh0, bh1, bl0, bl1);
                }
            }
            #pragma unroll
            for (int si = 0; si < 3; si++) {
                int slab = 3 * mg + si;
                int r0 = slab * 16 + ln;
                if (r0 < 64) {
                    float br0 = __ldg(br + r0), br1 = __ldg(br + r0 + 8);
                    #pragma unroll
                    for (int j = 0; j < 4; j++) {
                        int c0 = cb + j * 8 + 2 * lk;
                        float2 h0 = *(const float2*)(hsrc + (size_t)r0 * T + c0);
                        float2 h1 = *(const float2*)(hsrc + (size_t)(r0 + 8) * T + c0);
                        float2 v0 = { acc[si][j][0] + br0 + h0.x, acc[si][j][1] + br0 + h0.y };
                        float2 v1 = { acc[si][j][2] + br1 + h1.x, acc[si][j][3] + br1 + h1.y };
                        *(float2*)(hdst + (size_t)r0 * T + c0) = v0;
                        *(float2*)(hdst + (size_t)(r0 + 8) * T + c0) = v1;
                    }
                } else {
                    int sk0 = r0 - 64;
                    float bs0 = __ldg(bs + sk0), bs1 = __ldg(bs + sk0 + 8);
                    #pragma unroll
                    for (int j = 0; j < 4; j++) {
                        int c0 = cb + j * 8 + 2 * lk;
                        float2* g0 = (float2*)(skp + (size_t)sk0 * T + c0);
                        float2* g1 = (float2*)(skp + (size_t)(sk0 + 8) * T + c0);
                        float2 v0 = { acc[si][j][0] + bs0, acc[si][j][1] + bs0 };
                        float2 v1 = { acc[si][j][2] + bs1, acc[si][j][3] + bs1 };
                        if (!first) {
                            float2 o0 = *g0, o1 = *g1;
                            v0.x += o0.x; v0.y += o0.y; v1.x += o1.x; v1.y += o1.y;
                        }
                        *g0 = v0; *g1 = v1;
                    }
                }
            }
        }
    }
}

// ---------------------------------------------------------------------------
// Kernel 3: head (fp32)
// ---------------------------------------------------------------------------
__global__ void __launch_bounds__(256) head_kernel(
    const float* __restrict__ w1, const float* __restrict__ b1,
    const float* __restrict__ w2, const float* __restrict__ b2,
    float* __restrict__ out)
{
    extern __shared__ float smem[];
    float* sk   = smem;
    float* part = smem + S * TT;

    const int b = blockIdx.y, t0 = blockIdx.x * TT;
    const int tid = threadIdx.x, wp = tid >> 5, l = tid & 31;
    const float* skg = g_skip + (size_t)b * S * T + t0;

    for (int f = tid; f < S * TT / 4; f += 256) {
        int row = f >> 5, col = f & 31;
        float4 v = ((const float4*)(skg + (size_t)row * T))[col];
        v.x = fmaxf(v.x, 0.f); v.y = fmaxf(v.y, 0.f);
        v.z = fmaxf(v.z, 0.f); v.w = fmaxf(v.w, 0.f);
        ((float4*)sk)[f] = v;
    }
    __syncthreads();

    const float4* sk4 = (const float4*)sk;
    float4 po = {0.f, 0.f, 0.f, 0.f};
    for (int s2 = wp * 16; s2 < wp * 16 + 16; s2++) {
        float4 u = {0.f, 0.f, 0.f, 0.f};
        const float* wrow = w1 + (s2 << 7);
        #pragma unroll 8
        for (int s1 = 0; s1 < S; s1++)
            fma4(u, __ldg(wrow + s1), sk4[(s1 << 5) + l]);
        float bb = __ldg(b1 + s2);
        u.x = fmaxf(u.x + bb, 0.f); u.y = fmaxf(u.y + bb, 0.f);
        u.z = fmaxf(u.z + bb, 0.f); u.w = fmaxf(u.w + bb, 0.f);
        fma4(po, __ldg(w2 + s2), u);
    }
    ((float4*)(part + wp * TT))[l] = po;
    __syncthreads();

    if (tid < TT) {
        float acc = __ldg(b2);
        #pragma unroll
        for (int ww = 0; ww < 8; ww++) acc += part[ww * TT + tid];
        out[(size_t)b * T + t0 + tid] = acc;
    }
}

// ---------------------------------------------------------------------------
extern "C" void kernel_launch(void* const* d_in, const int* in_sizes, int n_in,
                              void* d_out, int out_size) {
    const float* x        = (const float*)d_in[0];
    const float* w_in     = (const float*)d_in[1];
    const float* b_in     = (const float*)d_in[2];
    const float* w_causal = (const float*)d_in[3];
    const float* b_causal = (const float*)d_in[4];
    const float* w_filter = (const float*)d_in[5];
    const float* b_filter = (const float*)d_in[6];
    const float* w_gate   = (const float*)d_in[7];
    const float* b_gate   = (const float*)d_in[8];
    const float* w_res    = (const float*)d_in[9];
    const float* b_res    = (const float*)d_in[10];
    const float* w_skip   = (const float*)d_in[11];
    const float* b_skip   = (const float*)d_in[12];
    const float* w_out1   = (const float*)d_in[13];
    const float* b_out1   = (const float*)d_in[14];
    const float* w_out2   = (const float*)d_in[15];
    const float* b_out2   = (const float*)d_in[16];
    float* out = (float*)d_out;

    const int blk_smem  = 6 * TNW * 4;               // 110,592 B (2 CTAs/SM)
    const int head_smem = (S * TT + 8 * TT) * 4;     // 68 KB
    cudaFuncSetAttribute(block_kernel, cudaFuncAttributeMaxDynamicSharedMemorySize, blk_smem);
    cudaFuncSetAttribute(head_kernel,  cudaFuncAttributeMaxDynamicSharedMemorySize, head_smem);

    float* hbuf0;
    u32 *q1h, *q1l, *q2h, *q2l, *q3h, *q3l;
    cudaGetSymbolAddress((void**)&hbuf0, g_h);
    cudaGetSymbolAddress((void**)&q1h, g_q1h);
    cudaGetSymbolAddress((void**)&q1l, g_q1l);
    cudaGetSymbolAddress((void**)&q2h, g_q2h);
    cudaGetSymbolAddress((void**)&q2l, g_q2l);
    cudaGetSymbolAddress((void**)&q3h, g_q3h);
    cudaGetSymbolAddress((void**)&q3l, g_q3l);
    float* hbuf[2] = { hbuf0, hbuf0 + (size_t)BB * R * T };

    const int pre_total = NBLK * (Q1N + Q2N + Q3N);
    prep_kernel<<<(pre_total + 255) / 256, 256>>>(w_causal, w_filter, w_gate, w_res, w_skip);

    input_kernel<<<BB * R * T / 256, 256>>>(x, w_in, b_in);

    dim3 grid(T / TT, BB);
    for (int i = 0; i < NBLK; i++) {
        int d = 1 << (i & 7);
        block_kernel<<<grid, 256, blk_smem>>>(
            hbuf[i & 1], hbuf[(i + 1) & 1],
            (const uint4*)(q1h + (size_t)i * Q1N), (const uint4*)(q1l + (size_t)i * Q1N),
            b_causal + (size_t)i * R,
            (const uint4*)(q2h + (size_t)i * Q2N), (const uint4*)(q2l + (size_t)i * Q2N),
            b_filter + (size_t)i * R, b_gate + (size_t)i * R,
            (const uint4*)(q3h + (size_t)i * Q3N), (const uint4*)(q3l + (size_t)i * Q3N),
            b_res + (size_t)i * R, b_skip + (size_t)i * S,
            d, i == 0 ? 1 : 0);
    }

    head_kernel<<<grid, 256, head_smem>>>(w_out1, b_out1, w_out2, b_out2, out);
}

// round 17
// speedup vs baseline: 1.4584x; 1.1050x over previous
#include <cuda_runtime.h>
#include <cuda_bf16.h>

#define BB 8
#define T 32768
#define R 64
#define S 128
#define NBLK 24
#define TT 128
#define RS 136             // u32 words per ch-pair row (128 t + 8 pad); 136%32==8
#define PNW (32 * RS)      // u32 words per tensor plane (32 ch-pairs) = 4352

typedef unsigned int u32;
typedef unsigned short u16;

__device__ __align__(16) float g_h[2][BB * R * T];   // ping-pong fp32 residual stream
__device__ __align__(16) float g_skip[BB * S * T];   // fp32 skip accumulator

// Fragment-ordered bf16 weights (packed pairs), hi + lo split, built by prep_kernel.
#define Q1N 4096
#define Q2N 4096
#define Q3N 6144
__device__ __align__(16) u32 g_q1h[NBLK * Q1N], g_q1l[NBLK * Q1N];
__device__ __align__(16) u32 g_q2h[NBLK * Q2N], g_q2l[NBLK * Q2N];
__device__ __align__(16) u32 g_q3h[NBLK * Q3N], g_q3l[NBLK * Q3N];

// MUFU-based gated activation (error ~1e-6, negligible vs bf16-split 2^-18 scheme)
__device__ __forceinline__ float fast_tanh(float x) {
    x = fminf(fmaxf(x, -15.f), 15.f);
    float e = __expf(2.f * x);
    return __fdividef(e - 1.f, e + 1.f);
}
__device__ __forceinline__ float fast_sig(float x) {
    return __fdividef(1.f, 1.f + __expf(-x));
}

__device__ __forceinline__ void split2(float v, u16 &h, u16 &lo) {
    __nv_bfloat16 bh = __float2bfloat16_rn(v);
    h = __bfloat16_as_ushort(bh);
    lo = __bfloat16_as_ushort(__float2bfloat16_rn(v - __bfloat162float(bh)));
}

// store fp32 value as bf16 hi/lo into [ch-pair][t] packed tensor at (channel r, time c)
__device__ __forceinline__ void store_split(u32* hiBase, int c, int r, float v) {
    u16 h, lo;
    split2(v, h, lo);
    int w = (r >> 1) * RS + c;
    ((u16*)hiBase)[2 * w + (r & 1)] = h;
    ((u16*)(hiBase + PNW))[2 * w + (r & 1)] = lo;
}

#define MMAB(d, a, b0, b1) \
    asm("mma.sync.aligned.m16n8k16.row.col.f32.bf16.bf16.f32 " \
        "{%0,%1,%2,%3}, {%4,%5,%6,%7}, {%8,%9}, {%0,%1,%2,%3};" \
        : "+f"(d[0]), "+f"(d[1]), "+f"(d[2]), "+f"(d[3]) \
        : "r"(a.x), "r"(a.y), "r"(a.z), "r"(a.w), "r"(b0), "r"(b1))

// 3-product bf16 scheme: Ah*Bh + Ah*Bl + Al*Bh
#define MMA3(d, Ah, Al, bh0, bh1, bl0, bl1) do { \
    MMAB(d, Ah, bh0, bh1);                       \
    MMAB(d, Ah, bl0, bl1);                       \
    MMAB(d, Al, bh0, bh1);                       \
} while (0)

__device__ __forceinline__ void fma4(float4 &a, float w, const float4 &v) {
    a.x = fmaf(w, v.x, a.x); a.y = fmaf(w, v.y, a.y);
    a.z = fmaf(w, v.z, a.z); a.w = fmaf(w, v.w, a.w);
}

// ---------------------------------------------------------------------------
// Prep: fragment-ordered bf16 hi/lo weight pairs (once per launch)
// ---------------------------------------------------------------------------
__global__ void prep_kernel(const float* __restrict__ wc, const float* __restrict__ wf,
                            const float* __restrict__ wg, const float* __restrict__ wr,
                            const float* __restrict__ ws) {
    int idx = blockIdx.x * blockDim.x + threadIdx.x;
    const int PER = Q1N + Q2N + Q3N;
    if (idx >= NBLK * PER) return;
    int lyr = idx / PER;
    int e = idx % PER;
    float w0, w1; u32 *dh, *dl;
    if (e < Q1N) {
        int slab = e >> 10, kt = (e >> 7) & 7, lane = (e >> 2) & 31, r = e & 3;
        int row = slab * 16 + (lane >> 2) + 8 * (r & 1);
        int k = kt * 16 + 2 * (lane & 3) + 8 * (r >> 1);
        #define WC(kk) ((kk) < 64 ? wc[(((size_t)lyr * 64 + row) * 64 + (kk)) * 2] \
                                  : wc[(((size_t)lyr * 64 + row) * 64 + (kk) - 64) * 2 + 1])
        w0 = WC(k); w1 = WC(k + 1);
        #undef WC
        dh = g_q1h + (size_t)lyr * Q1N + e;
        dl = g_q1l + (size_t)lyr * Q1N + e;
    } else if (e < Q1N + Q2N) {
        int e2 = e - Q1N;
        int slab = e2 >> 9, kt = (e2 >> 7) & 3, lane = (e2 >> 2) & 31, r = e2 & 3;
        int row = (lane >> 2) + 8 * (r & 1);           // 0..15 within tile
        int ch = slab * 8 + (row & 7);
        int k = kt * 16 + 2 * (lane & 3) + 8 * (r >> 1);
        const float* src = (row < 8) ? wf : wg;
        w0 = src[((size_t)lyr * 64 + ch) * 64 + k];
        w1 = src[((size_t)lyr * 64 + ch) * 64 + k + 1];
        dh = g_q2h + (size_t)lyr * Q2N + e2;
        dl = g_q2l + (size_t)lyr * Q2N + e2;
    } else {
        int e3 = e - Q1N - Q2N;
        int slab = e3 >> 9, kt = (e3 >> 7) & 3, lane = (e3 >> 2) & 31, r = e3 & 3;
        int grow = slab * 16 + (lane >> 2) + 8 * (r & 1);  // 0..191
        int k = kt * 16 + 2 * (lane & 3) + 8 * (r >> 1);
        if (grow < 64) {
            w0 = wr[((size_t)lyr * 64 + grow) * 64 + k];
            w1 = wr[((size_t)lyr * 64 + grow) * 64 + k + 1];
        } else {
            w0 = ws[((size_t)lyr * 128 + grow - 64) * 64 + k];
            w1 = ws[((size_t)lyr * 128 + grow - 64) * 64 + k + 1];
        }
        dh = g_q3h + (size_t)lyr * Q3N + e3;
        dl = g_q3l + (size_t)lyr * Q3N + e3;
    }
    u16 h0, l0, h1, l1;
    split2(w0, h0, l0);
    split2(w1, h1, l1);
    *dh = ((u32)h1 << 16) | h0;
    *dl = ((u32)l1 << 16) | l0;
}

// ---------------------------------------------------------------------------
// Kernel 1: input 1x1 conv
// ---------------------------------------------------------------------------
__global__ void input_kernel(const float* __restrict__ x,
                             const float* __restrict__ w_in,
                             const float* __restrict__ b_in) {
    int idx = blockIdx.x * blockDim.x + threadIdx.x;
    int t = idx & (T - 1);
    int r = (idx >> 15) & (R - 1);
    int b = idx >> 21;
    g_h[0][idx] = fmaf(__ldg(&w_in[r]), __ldg(&x[b * T + t]), __ldg(&b_in[r]));
}

// ---------------------------------------------------------------------------
// Kernel 2: fused WaveNet block, bf16 m16n8k16 3-product.
// [ch-pair][t] smem layout (RS=136): phase-0 global loads coalesced along t,
// B-fragment LDS conflict-free (bank = 8*lk + ln).
// ---------------------------------------------------------------------------
__global__ void __launch_bounds__(256, 2) block_kernel(
    const float* __restrict__ h_in, float* __restrict__ h_out,
    const uint4* __restrict__ q1h, const uint4* __restrict__ q1l, const float* __restrict__ bc,
    const uint4* __restrict__ q2h, const uint4* __restrict__ q2l, const float* __restrict__ bf,
    const float* __restrict__ bg,
    const uint4* __restrict__ q3h, const uint4* __restrict__ q3l, const float* __restrict__ br,
    const float* __restrict__ bs,
    int d, int first)
{
    extern __shared__ u32 sm32[];
    u32* s_hp = sm32;               // h(t-d) hi; lo at +PNW   (reused as 'a' later)
    u32* s_hn = sm32 + 2 * PNW;     // h(t)   hi; lo at +PNW
    u32* s_z  = sm32 + 4 * PNW;     // z      hi; lo at +PNW

    const int b = blockIdx.y, t0 = blockIdx.x * TT;
    const int tid = threadIdx.x, wp = tid >> 5, l = tid & 31;
    const int lk = l & 3, ln = l >> 2;
    const float* hbase = h_in + (size_t)b * R * T;

    // ---- Phase 0: load fp32 h (coalesced along t), bf16-split into smem ----
    for (int idx = tid; idx < 1024; idx += 256) {
        int c4 = idx & 31, rp = idx >> 5;   // float4 col (lane-varying), ch-pair
        float4 v0 = ((const float4*)(hbase + (size_t)(2 * rp) * T + t0))[c4];
        float4 v1 = ((const float4*)(hbase + (size_t)(2 * rp + 1) * T + t0))[c4];
        const float* e0 = (const float*)&v0;
        const float* e1 = (const float*)&v1;
        #pragma unroll
        for (int i = 0; i < 4; i++) {
            u16 h0, l0, h1, l1;
            split2(e0[i], h0, l0);
            split2(e1[i], h1, l1);
            s_hn[rp * RS + c4 * 4 + i] = ((u32)h1 << 16) | h0;
            s_hn[rp * RS + c4 * 4 + i + PNW] = ((u32)l1 << 16) | l0;
        }
    }
    if ((d & 3) == 0) {
        const int dq = d >> 2;
        for (int idx = tid; idx < 1024; idx += 256) {
            int c4 = idx & 31, rp = idx >> 5;
            int tq = (t0 >> 2) + c4 - dq;
            float4 v0, v1;
            if (tq >= 0) {
                v0 = ((const float4*)(hbase + (size_t)(2 * rp) * T))[tq];
                v1 = ((const float4*)(hbase + (size_t)(2 * rp + 1) * T))[tq];
            } else {
                v0 = make_float4(0.f, 0.f, 0.f, 0.f);
                v1 = v0;
            }
            const float* e0 = (const float*)&v0;
            const float* e1 = (const float*)&v1;
            #pragma unroll
            for (int i = 0; i < 4; i++) {
                u16 h0, l0, h1, l1;
                split2(e0[i], h0, l0);
                split2(e1[i], h1, l1);
                s_hp[rp * RS + c4 * 4 + i] = ((u32)h1 << 16) | h0;
                s_hp[rp * RS + c4 * 4 + i + PNW] = ((u32)l1 << 16) | l0;
            }
        }
    } else {
        for (int idx = tid; idx < 4096; idx += 256) {
            int t = idx & 127, rp = idx >> 7;   // t lane-varying -> coalesced
            int ts = t0 + t - d;
            float a0 = 0.f, a1 = 0.f;
            if (ts >= 0) {
                a0 = hbase[(size_t)(2 * rp) * T + ts];
                a1 = hbase[(size_t)(2 * rp + 1) * T + ts];
            }
            u16 h0, l0, h1, l1;
            split2(a0, h0, l0);
            split2(a1, h1, l1);
            s_hp[rp * RS + t] = ((u32)h1 << 16) | h0;
            s_hp[rp * RS + t + PNW] = ((u32)l1 << 16) | l0;
        }
    }
    __syncthreads();

    // ---- Phase 1: z = Wc x [hp; hn]  (2 slabs x 32 cols per warp) ----
    {
        const int mg = wp >> 2, cg = wp & 3;
        const int cb = cg * 32;
        const int s0 = 2 * mg, s1 = s0 + 1;
        float acc0[4][4], acc1[4][4];
        #pragma unroll
        for (int j = 0; j < 4; j++) {
            acc0[j][0] = acc0[j][1] = acc0[j][2] = acc0[j][3] = 0.f;
            acc1[j][0] = acc1[j][1] = acc1[j][2] = acc1[j][3] = 0.f;
        }
        #pragma unroll 2
        for (int kt = 0; kt < 8; kt++) {
            uint4 Ah0 = __ldg(&q1h[(s0 * 8 + kt) * 32 + l]);
            uint4 Al0 = __ldg(&q1l[(s0 * 8 + kt) * 32 + l]);
            uint4 Ah1 = __ldg(&q1h[(s1 * 8 + kt) * 32 + l]);
            uint4 Al1 = __ldg(&q1l[(s1 * 8 + kt) * 32 + l]);
            const u32* bh = ((kt < 4) ? s_hp : s_hn) + ((kt & 3) * 8 + lk) * RS + cb + ln;
            #pragma unroll
            for (int j = 0; j < 4; j++) {
                u32 bh0 = bh[j * 8], bh1 = bh[j * 8 + 4 * RS];
                u32 bl0 = bh[j * 8 + PNW], bl1 = bh[j * 8 + 4 * RS + PNW];
                MMA3(acc0[j], Ah0, Al0, bh0, bh1, bl0, bl1);
                MMA3(acc1[j], Ah1, Al1, bh0, bh1, bl0, bl1);
            }
        }
        #pragma unroll
        for (int si = 0; si < 2; si++) {
            float (*ac)[4] = si ? acc1 : acc0;
            int r0 = (2 * mg + si) * 16 + ln;
            float bv0 = __ldg(bc + r0), bv1 = __ldg(bc + r0 + 8);
            #pragma unroll
            for (int j = 0; j < 4; j++) {
                int c0 = cb + j * 8 + 2 * lk;
                store_split(s_z, c0,     r0,     ac[j][0] + bv0);
                store_split(s_z, c0 + 1, r0,     ac[j][1] + bv0);
                store_split(s_z, c0,     r0 + 8, ac[j][2] + bv1);
                store_split(s_z, c0 + 1, r0 + 8, ac[j][3] + bv1);
            }
        }
    }
    __syncthreads();

    // ---- Phase 2: a = tanh(Wf z + bf) * sigmoid(Wg z + bg)  (4 slabs x 32 cols) ----
    // No interior barrier: MMAs read s_z only; epilogue writes s_hp only.
    {
        const int mg = wp >> 2, cg = wp & 3;
        const int cb = cg * 32;
        float acc[4][4][4];
        #pragma unroll
        for (int si = 0; si < 4; si++)
            #pragma unroll
            for (int j = 0; j < 4; j++)
                acc[si][j][0] = acc[si][j][1] = acc[si][j][2] = acc[si][j][3] = 0.f;
        #pragma unroll
        for (int kt = 0; kt < 4; kt++) {
            uint4 Ah[4], Al[4];
            #pragma unroll
            for (int si = 0; si < 4; si++) {
                int slab = 4 * mg + si;
                Ah[si] = __ldg(&q2h[(slab * 4 + kt) * 32 + l]);
                Al[si] = __ldg(&q2l[(slab * 4 + kt) * 32 + l]);
            }
            const u32* bh = s_z + (kt * 8 + lk) * RS + cb + ln;
            #pragma unroll
            for (int j = 0; j < 4; j++) {
                u32 bh0 = bh[j * 8], bh1 = bh[j * 8 + 4 * RS];
                u32 bl0 = bh[j * 8 + PNW], bl1 = bh[j * 8 + 4 * RS + PNW];
                #pragma unroll
                for (int si = 0; si < 4; si++)
                    MMA3(acc[si][j], Ah[si], Al[si], bh0, bh1, bl0, bl1);
            }
        }
        #pragma unroll
        for (int si = 0; si < 4; si++) {
            int slab = 4 * mg + si;
            int ch = slab * 8 + ln;
            float bfv = __ldg(bf + ch), bgv = __ldg(bg + ch);
            #pragma unroll
            for (int j = 0; j < 4; j++) {
                int c0 = cb + j * 8 + 2 * lk;
                float a0 = fast_tanh(acc[si][j][0] + bfv) * fast_sig(acc[si][j][2] + bgv);
                float a1 = fast_tanh(acc[si][j][1] + bfv) * fast_sig(acc[si][j][3] + bgv);
                store_split(s_hp, c0,     ch, a0);   // a overwrites hp
                store_split(s_hp, c0 + 1, ch, a1);
            }
        }
    }
    __syncthreads();

    // ---- Phase 3: res (slabs 0-3) + skip (slabs 4-11)  (3 slabs x 32 cols, x2) ----
    {
        float* hdst = h_out + (size_t)b * R * T + t0;
        const float* hsrc = h_in + (size_t)b * R * T + t0;
        float* skp = g_skip + (size_t)b * S * T + t0;
        #pragma unroll
        for (int ui = 0; ui < 2; ui++) {
            int u = wp + ui * 8;          // 0..15
            int mg = u >> 2, cg = u & 3;
            int cb = cg * 32;
            float acc[3][4][4];
            #pragma unroll
            for (int si = 0; si < 3; si++)
                #pragma unroll
                for (int j = 0; j < 4; j++)
                    acc[si][j][0] = acc[si][j][1] = acc[si][j][2] = acc[si][j][3] = 0.f;
            #pragma unroll
            for (int kt = 0; kt < 4; kt++) {
                uint4 Ah[3], Al[3];
                #pragma unroll
                for (int si = 0; si < 3; si++) {
                    int slab = 3 * mg + si;
                    Ah[si] = __ldg(&q3h[(slab * 4 + kt) * 32 + l]);
                    Al[si] = __ldg(&q3l[(slab * 4 + kt) * 32 + l]);
                }
                const u32* bh = s_hp + (kt * 8 + lk) * RS + cb + ln;
                #pragma unroll
                for (int j = 0; j < 4; j++) {
                    u32 bh0 = bh[j * 8], bh1 = bh[j * 8 + 4 * RS];
                    u32 bl0 = bh[j * 8 + PNW], bl1 = bh[j * 8 + 4 * RS + PNW];
                    #pragma unroll
                    for (int si = 0; si < 3; si++)
                        MMA3(acc[si][j], Ah[si], Al[si], bh0, bh1, bl0, bl1);
                }
            }
            #pragma unroll
            for (int si = 0; si < 3; si++) {
                int slab = 3 * mg + si;
                int r0 = slab * 16 + ln;
                if (r0 < 64) {
                    float br0 = __ldg(br + r0), br1 = __ldg(br + r0 + 8);
                    #pragma unroll
                    for (int j = 0; j < 4; j++) {
                        int c0 = cb + j * 8 + 2 * lk;
                        float2 h0 = *(const float2*)(hsrc + (size_t)r0 * T + c0);
                        float2 h1 = *(const float2*)(hsrc + (size_t)(r0 + 8) * T + c0);
                        float2 v0 = { acc[si][j][0] + br0 + h0.x, acc[si][j][1] + br0 + h0.y };
                        float2 v1 = { acc[si][j][2] + br1 + h1.x, acc[si][j][3] + br1 + h1.y };
                        *(float2*)(hdst + (size_t)r0 * T + c0) = v0;
                        *(float2*)(hdst + (size_t)(r0 + 8) * T + c0) = v1;
                    }
                } else {
                    int sk0 = r0 - 64;
                    float bs0 = __ldg(bs + sk0), bs1 = __ldg(bs + sk0 + 8);
                    #pragma unroll
                    for (int j = 0; j < 4; j++) {
                        int c0 = cb + j * 8 + 2 * lk;
                        float2* g0 = (float2*)(skp + (size_t)sk0 * T + c0);
                        float2* g1 = (float2*)(skp + (size_t)(sk0 + 8) * T + c0);
                        float2 v0 = { acc[si][j][0] + bs0, acc[si][j][1] + bs0 };
                        float2 v1 = { acc[si][j][2] + bs1, acc[si][j][3] + bs1 };
                        if (!first) {
                            float2 o0 = *g0, o1 = *g1;
                            v0.x += o0.x; v0.y += o0.y; v1.x += o1.x; v1.y += o1.y;
                        }
                        *g0 = v0; *g1 = v1;
                    }
                }
            }
        }
    }
}

// ---------------------------------------------------------------------------
// Kernel 3: head (fp32)
// ---------------------------------------------------------------------------
__global__ void __launch_bounds__(256) head_kernel(
    const float* __restrict__ w1, const float* __restrict__ b1,
    const float* __restrict__ w2, const float* __restrict__ b2,
    float* __restrict__ out)
{
    extern __shared__ float smem[];
    float* sk   = smem;
    float* part = smem + S * TT;

    const int b = blockIdx.y, t0 = blockIdx.x * TT;
    const int tid = threadIdx.x, wp = tid >> 5, l = tid & 31;
    const float* skg = g_skip + (size_t)b * S * T + t0;

    for (int f = tid; f < S * TT / 4; f += 256) {
        int row = f >> 5, col = f & 31;
        float4 v = ((const float4*)(skg + (size_t)row * T))[col];
        v.x = fmaxf(v.x, 0.f); v.y = fmaxf(v.y, 0.f);
        v.z = fmaxf(v.z, 0.f); v.w = fmaxf(v.w, 0.f);
        ((float4*)sk)[f] = v;
    }
    __syncthreads();

    const float4* sk4 = (const float4*)sk;
    float4 po = {0.f, 0.f, 0.f, 0.f};
    for (int s2 = wp * 16; s2 < wp * 16 + 16; s2++) {
        float4 u = {0.f, 0.f, 0.f, 0.f};
        const float* wrow = w1 + (s2 << 7);
        #pragma unroll 8
        for (int s1 = 0; s1 < S; s1++)
            fma4(u, __ldg(wrow + s1), sk4[(s1 << 5) + l]);
        float bb = __ldg(b1 + s2);
        u.x = fmaxf(u.x + bb, 0.f); u.y = fmaxf(u.y + bb, 0.f);
        u.z = fmaxf(u.z + bb, 0.f); u.w = fmaxf(u.w + bb, 0.f);
        fma4(po, __ldg(w2 + s2), u);
    }
    ((float4*)(part + wp * TT))[l] = po;
    __syncthreads();

    if (tid < TT) {
        float acc = __ldg(b2);
        #pragma unroll
        for (int ww = 0; ww < 8; ww++) acc += part[ww * TT + tid];
        out[(size_t)b * T + t0 + tid] = acc;
    }
}

// ---------------------------------------------------------------------------
extern "C" void kernel_launch(void* const* d_in, const int* in_sizes, int n_in,
                              void* d_out, int out_size) {
    const float* x        = (const float*)d_in[0];
    const float* w_in     = (const float*)d_in[1];
    const float* b_in     = (const float*)d_in[2];
    const float* w_causal = (const float*)d_in[3];
    const float* b_causal = (const float*)d_in[4];
    const float* w_filter = (const float*)d_in[5];
    const float* b_filter = (const float*)d_in[6];
    const float* w_gate   = (const float*)d_in[7];
    const float* b_gate   = (const float*)d_in[8];
    const float* w_res    = (const float*)d_in[9];
    const float* b_res    = (const float*)d_in[10];
    const float* w_skip   = (const float*)d_in[11];
    const float* b_skip   = (const float*)d_in[12];
    const float* w_out1   = (const float*)d_in[13];
    const float* b_out1   = (const float*)d_in[14];
    const float* w_out2   = (const float*)d_in[15];
    const float* b_out2   = (const float*)d_in[16];
    float* out = (float*)d_out;

    const int blk_smem  = 6 * PNW * 4;               // 104,448 B (2 CTAs/SM)
    const int head_smem = (S * TT + 8 * TT) * 4;     // 68 KB
    cudaFuncSetAttribute(block_kernel, cudaFuncAttributeMaxDynamicSharedMemorySize, blk_smem);
    cudaFuncSetAttribute(head_kernel,  cudaFuncAttributeMaxDynamicSharedMemorySize, head_smem);

    float* hbuf0;
    u32 *q1h, *q1l, *q2h, *q2l, *q3h, *q3l;
    cudaGetSymbolAddress((void**)&hbuf0, g_h);
    cudaGetSymbolAddress((void**)&q1h, g_q1h);
    cudaGetSymbolAddress((void**)&q1l, g_q1l);
    cudaGetSymbolAddress((void**)&q2h, g_q2h);
    cudaGetSymbolAddress((void**)&q2l, g_q2l);
    cudaGetSymbolAddress((void**)&q3h, g_q3h);
    cudaGetSymbolAddress((void**)&q3l, g_q3l);
    float* hbuf[2] = { hbuf0, hbuf0 + (size_t)BB * R * T };

    const int pre_total = NBLK * (Q1N + Q2N + Q3N);
    prep_kernel<<<(pre_total + 255) / 256, 256>>>(w_causal, w_filter, w_gate, w_res, w_skip);

    input_kernel<<<BB * R * T / 256, 256>>>(x, w_in, b_in);

    dim3 grid(T / TT, BB);
    for (int i = 0; i < NBLK; i++) {
        int d = 1 << (i & 7);
        block_kernel<<<grid, 256, blk_smem>>>(
            hbuf[i & 1], hbuf[(i + 1) & 1],
            (const uint4*)(q1h + (size_t)i * Q1N), (const uint4*)(q1l + (size_t)i * Q1N),
            b_causal + (size_t)i * R,
            (const uint4*)(q2h + (size_t)i * Q2N), (const uint4*)(q2l + (size_t)i * Q2N),
            b_filter + (size_t)i * R, b_gate + (size_t)i * R,
            (const uint4*)(q3h + (size_t)i * Q3N), (const uint4*)(q3l + (size_t)i * Q3N),
            b_res + (size_t)i * R, b_skip + (size_t)i * S,
            d, i == 0 ? 1 : 0);
    }

    head_kernel<<<grid, 256, head_smem>>>(w_out1, b_out1, w_out2, b_out2, out);
}